// round 9
// baseline (speedup 1.0000x reference)
#include <cuda_runtime.h>
#include <cstdint>

// ---------------- problem constants ----------------
#define SQ    4096          // sequence length
#define EMBD  256
#define HDIRD 256           // HID/2
#define NG    1024          // 4*HDIR
#define TAGS  10
#define NEGV  -10000.0f
#define CL    8             // cluster size per direction
#define HPAD  132           // padded half stride in floats (128+4 -> halves in different banks)
#define HBSTR 264           // one buffer = 2 halves = 264 floats

// ---------------- scratch (device globals; no dynamic alloc) ----------------
__device__ float g_x[SQ * EMBD];              // gathered embeddings   4 MB
__device__ float g_xw[2][SQ * NG];            // input-gate precompute 32 MB
__device__ float g_h[2][SQ * HDIRD];          // hidden states         8 MB
__device__ float g_feats[SQ * TAGS];          // CRF emission feats

// ---------------- helpers ----------------
__device__ __forceinline__ uint32_t smem_u32(const void* p) {
    return (uint32_t)__cvta_generic_to_shared(p);
}
__device__ __forceinline__ uint32_t mapa_u32(uint32_t laddr, uint32_t rank) {
    uint32_t rem;
    asm("mapa.shared::cluster.u32 %0, %1, %2;" : "=r"(rem) : "r"(laddr), "r"(rank));
    return rem;
}
__device__ __forceinline__ void st_remote_f32(uint32_t raddr, float v) {
    asm volatile("st.shared::cluster.f32 [%0], %1;" :: "r"(raddr), "f"(v) : "memory");
}
#define CLUSTER_ARRIVE_() \
    asm volatile("barrier.cluster.arrive.aligned;" ::: "memory")
#define CLUSTER_WAIT_() \
    asm volatile("barrier.cluster.wait.aligned;" ::: "memory")
#define CLUSTER_SYNC_() do { CLUSTER_ARRIVE_(); CLUSTER_WAIT_(); } while (0)

__device__ __forceinline__ void fma2(unsigned long long& d,
                                     unsigned long long a, unsigned long long b) {
    asm("fma.rn.f32x2 %0, %1, %2, %0;" : "+l"(d) : "l"(a), "l"(b));
}

__device__ __forceinline__ float sigm_f(float x) {
    return 1.0f / (1.0f + __expf(-x));
}
__device__ __forceinline__ float tanh_f(float x) {
    float e = __expf(-2.0f * fabsf(x));
    float r = (1.0f - e) / (1.0f + e);
    return copysignf(r, x);
}

// ---------------- kernel 1: embedding gather ----------------
__global__ void gather_k(const int* __restrict__ sent, const float* __restrict__ emb) {
    int gid = blockIdx.x * blockDim.x + threadIdx.x;  // over SQ*64 float4
    int row = gid >> 6;
    int c   = gid & 63;
    ((float4*)g_x)[row * 64 + c] =
        ((const float4*)emb)[(size_t)sent[row] * 64 + c];
}

// ---------------- kernel 2: xw = x @ Wih^T + (bih+bhh), both directions ----------------
__global__ void xw_gemm_k(const float* __restrict__ Wf, const float* __restrict__ Wb,
                          const float* __restrict__ bihf, const float* __restrict__ bhhf,
                          const float* __restrict__ bihb, const float* __restrict__ bhhb) {
    int d = blockIdx.z;
    const float* W  = d ? Wb : Wf;
    const float* b1 = d ? bihb : bihf;
    const float* b2 = d ? bhhb : bhhf;

    __shared__ float As[32][65];
    __shared__ float Bs[32][65];

    int s0 = blockIdx.x * 64;
    int j0 = blockIdx.y * 64;
    int tid = threadIdx.x;
    int tx = tid & 15, ty = tid >> 4;

    float acc[4][4];
#pragma unroll
    for (int i = 0; i < 4; i++)
#pragma unroll
        for (int j = 0; j < 4; j++) acc[i][j] = 0.0f;

    for (int k0 = 0; k0 < EMBD; k0 += 32) {
#pragma unroll
        for (int i = 0; i < 8; i++) {
            int idx = i * 256 + tid;
            int si = idx >> 5, e = idx & 31;
            As[e][si] = g_x[(s0 + si) * EMBD + k0 + e];
            Bs[e][si] = W[(j0 + si) * EMBD + k0 + e];
        }
        __syncthreads();
#pragma unroll
        for (int e = 0; e < 32; e++) {
            float a[4], bb[4];
#pragma unroll
            for (int i = 0; i < 4; i++) { a[i] = As[e][ty * 4 + i]; bb[i] = Bs[e][tx * 4 + i]; }
#pragma unroll
            for (int i = 0; i < 4; i++)
#pragma unroll
                for (int j = 0; j < 4; j++) acc[i][j] = fmaf(a[i], bb[j], acc[i][j]);
        }
        __syncthreads();
    }
#pragma unroll
    for (int i = 0; i < 4; i++)
#pragma unroll
        for (int j = 0; j < 4; j++) {
            int jj = j0 + tx * 4 + j;
            g_xw[d][(s0 + ty * 4 + i) * NG + jj] = acc[i][j] + b1[jj] + b2[jj];
        }
}

// ---------------- kernel 3: recurrent LSTM, one 8-CTA cluster per direction ----------------
// Proven cluster.sync protocol (R1/R8) + warp-local gates:
//   warp w owns local h-indices jl in [4w, 4w+4).
//   lane = gate*8 + (jl&3)*2 + half  ->  Whh row = gate*256 + r*32 + jl, column half.
// After the pair-reduce every lane holds z(row); three shfls deliver zf/zg/zo to
// the gate==0 lanes, which compute gates+c+h for their jl (dup per half; the two
// dup lanes split the 8 remote stores 4+4). One cluster.sync per step gives
// remote-store visibility AND buffer backpressure; no zbuf, no __syncthreads.
__global__ void __cluster_dims__(CL, 1, 1) __launch_bounds__(256, 1)
lstm_k(const float* __restrict__ Whhf, const float* __restrict__ Whhb) {
    int dir = blockIdx.y;
    const float* Whh = dir ? Whhb : Whhf;
    const float* xw  = g_xw[dir];
    int r    = blockIdx.x;          // cluster rank
    int tid  = threadIdx.x;
    int w    = tid >> 5;
    int lane = tid & 31;
    int g    = lane >> 3;           // gate 0..3 (i,f,g,o)
    int sub  = lane & 7;            // 2*j' + half
    int jl   = (w << 2) + (sub >> 1);   // local h index 0..31
    int half = sub & 1;             // column half
    int gidx = r * 32 + jl;         // global h index
    int grow = g * HDIRD + gidx;    // Whh row / xw column

    // weights -> registers, packed as f32 pairs (half row = 128 cols)
    ulonglong2 Wp[32];
    const ulonglong2* wsrc =
        (const ulonglong2*)(Whh + (size_t)grow * HDIRD + half * 128);
#pragma unroll
    for (int k = 0; k < 32; k++) Wp[k] = wsrc[k];

    __shared__ __align__(16) float hbuf[2 * HBSTR];   // halves padded by 16B

    for (int i = tid; i < 2 * HBSTR; i += 256) hbuf[i] = 0.0f;
    __syncthreads();
    CLUSTER_SYNC_();   // zeroed hbuf visible cluster-wide

    // hoisted remote store addresses (used by gate==0 lanes):
    // padded slot for global h index gidx: gidx (+4 if this CTA's chunk is in half1)
    uint32_t hb0 = smem_u32(hbuf);
    uint32_t hoff4 = (uint32_t)(gidx + ((r >= 4) ? 4 : 0)) * 4u;
    uint32_t rst[4];                 // this dup-lane's 4 destination ranks
#pragma unroll
    for (int s = 0; s < 4; s++)
        rst[s] = mapa_u32(hb0, (uint32_t)(half * 4 + s)) + hoff4;

    float c = 0.0f;
    int pos0 = dir ? (SQ - 1) : 0;
    float xwreg = xw[(size_t)pos0 * NG + grow];   // every lane: its own row's xw

    for (int t = 0; t < SQ; t++) {
        int p = t & 1;

        const ulonglong2* h2 =
            (const ulonglong2*)(hbuf + p * HBSTR + half * HPAD);
        unsigned long long a0 = 0ull, a1 = 0ull;
#pragma unroll
        for (int k = 0; k < 32; k++) {
            ulonglong2 hv = h2[k];
            fma2(a0, Wp[k].x, hv.x);
            fma2(a1, Wp[k].y, hv.y);
        }
        float2 f0 = *(float2*)&a0;
        float2 f1 = *(float2*)&a1;
        float acc = (f0.x + f0.y) + (f1.x + f1.y);
        acc += __shfl_xor_sync(0xffffffffu, acc, 1);   // combine column halves
        float z = acc + xwreg;

        // warp-local transpose: deliver zf/zg/zo to the gate==0 lanes
        float zf = __shfl_sync(0xffffffffu, z, sub + 8);
        float zg = __shfl_sync(0xffffffffu, z, sub + 16);
        float zo = __shfl_sync(0xffffffffu, z, sub + 24);

        int tn = t + 1;
        float hn = 0.0f;
        if (g == 0) {   // lanes 0..7 of every warp (dup per half)
            float ig = sigm_f(z);
            float fg = sigm_f(zf);
            float gg = tanh_f(zg);
            float og = sigm_f(zo);
            c = fmaf(fg, c, ig * gg);
            hn = og * tanh_f(c);

            if (tn < SQ) {   // remote broadcast into buffer p^1
                uint32_t bo = (uint32_t)((p ^ 1) * HBSTR * 4);
#pragma unroll
                for (int s = 0; s < 4; s++) st_remote_f32(rst[s] + bo, hn);
            }
        }

        CLUSTER_ARRIVE_();   // release: remote stores ordered before peers' wait

        // hidden behind barrier latency: result store + next xw load
        if (g == 0 && !half) {
            int pos = dir ? (SQ - 1 - t) : t;
            g_h[dir][(size_t)pos * HDIRD + gidx] = hn;
        }
        if (tn < SQ) {
            int pos = dir ? (SQ - 1 - tn) : tn;
            xwreg = xw[(size_t)pos * NG + grow];
        }

        CLUSTER_WAIT_();     // h(t) visible everywhere; buffers flip
    }
}

// ---------------- kernel 4: feats = [h_f | h_b] @ Wout^T + b (warp per s) ----------------
__global__ void feats_k(const float* __restrict__ Wout, const float* __restrict__ bout) {
    __shared__ float Wsm[TAGS][512];
    __shared__ float bsm[TAGS];
    int tid = threadIdx.x;
    for (int i = tid; i < TAGS * 512; i += 256) Wsm[i / 512][i % 512] = Wout[i];
    if (tid < TAGS) bsm[tid] = bout[tid];
    __syncthreads();

    int lane = tid & 31;
    int s = blockIdx.x * 8 + (tid >> 5);     // warp per sequence position
    float acc[TAGS];
#pragma unroll
    for (int t = 0; t < TAGS; t++) acc[t] = 0.0f;

#pragma unroll
    for (int d = 0; d < 2; d++) {
        const float* hrow = (d == 0) ? &g_h[0][(size_t)s * HDIRD]
                                     : &g_h[1][(size_t)s * HDIRD];
#pragma unroll
        for (int k0 = 0; k0 < HDIRD; k0 += 32) {
            float x = hrow[k0 + lane];
#pragma unroll
            for (int t = 0; t < TAGS; t++)
                acc[t] = fmaf(x, Wsm[t][d * 256 + k0 + lane], acc[t]);
        }
    }
#pragma unroll
    for (int t = 0; t < TAGS; t++) {
#pragma unroll
        for (int o = 16; o > 0; o >>= 1) acc[t] += __shfl_xor_sync(0xffffffffu, acc[t], o);
    }
    if (lane == 0) {
#pragma unroll
        for (int t = 0; t < TAGS; t++) g_feats[s * TAGS + t] = acc[t] + bsm[t];
    }
}

// ---------------- kernel 5: Viterbi decode (single warp) ----------------
__global__ void viterbi_k(const float* __restrict__ trans, float* __restrict__ out,
                          int out_size) {
    __shared__ unsigned char bp[SQ][TAGS];   // 40 KB backpointers
    int n = threadIdx.x;

    float tr[TAGS];
#pragma unroll
    for (int p = 0; p < TAGS; p++) tr[p] = (n < TAGS) ? trans[n * TAGS + p] : NEGV;

    float fvr = (n == 8) ? 0.0f : NEGV;      // START = 8
    float fa = (n < TAGS) ? g_feats[0 * TAGS + n] : 0.0f;
    float fb = (n < TAGS) ? g_feats[1 * TAGS + n] : 0.0f;

    for (int t = 0; t < SQ; t++) {
        float m = -3.4e38f;
        int bi = 0;
#pragma unroll
        for (int p = 0; p < TAGS; p++) {
            float v = __shfl_sync(0xffffffffu, fvr, p) + tr[p];
            if (v > m) { m = v; bi = p; }    // strict > keeps first max (jnp.argmax)
        }
        if (n < TAGS) bp[t][n] = (unsigned char)bi;
        float nf = m + fa;
        fa = fb;
        int tn = t + 2;
        if (n < TAGS && tn < SQ) fb = g_feats[tn * TAGS + n];
        fvr = nf;
    }

    float term = fvr + ((n < TAGS) ? trans[9 * TAGS + n] : NEGV);
    float bm = -3.4e38f;
    int bidx = 0;
#pragma unroll
    for (int p = 0; p < TAGS; p++) {
        float v = __shfl_sync(0xffffffffu, term, p);
        if (v > bm) { bm = v; bidx = p; }
    }
    if (n == 0) {
        int off = (out_size > SQ) ? 1 : 0;
        if (off) out[0] = bm;                // score first, then path
        int tag = bidx;
        for (int t = SQ - 1; t >= 0; t--) {
            out[off + t] = (float)tag;
            tag = bp[t][tag];
        }
    }
}

// ---------------- launch ----------------
extern "C" void kernel_launch(void* const* d_in, const int* in_sizes, int n_in,
                              void* d_out, int out_size) {
    const int*   sent  = (const int*)d_in[0];
    const float* emb   = (const float*)d_in[1];
    const float* Wih_f = (const float*)d_in[2];
    const float* Whh_f = (const float*)d_in[3];
    const float* bih_f = (const float*)d_in[4];
    const float* bhh_f = (const float*)d_in[5];
    const float* Wih_b = (const float*)d_in[6];
    const float* Whh_b = (const float*)d_in[7];
    const float* bih_b = (const float*)d_in[8];
    const float* bhh_b = (const float*)d_in[9];
    const float* W_out = (const float*)d_in[10];
    const float* b_out = (const float*)d_in[11];
    const float* trans = (const float*)d_in[12];
    float* out = (float*)d_out;

    gather_k<<<(SQ * 64) / 256, 256>>>(sent, emb);
    xw_gemm_k<<<dim3(SQ / 64, NG / 64, 2), 256>>>(Wih_f, Wih_b, bih_f, bhh_f, bih_b, bhh_b);
    lstm_k<<<dim3(CL, 2, 1), 256>>>(Whh_f, Whh_b);
    feats_k<<<SQ / 8, 256>>>(W_out, b_out);   // 512 blocks x 8 warps = 4096 positions
    viterbi_k<<<1, 32>>>(trans, out, out_size);
}

// round 10
// speedup vs baseline: 1.3743x; 1.3743x over previous
#include <cuda_runtime.h>
#include <cstdint>

// ---------------- problem constants ----------------
#define SQ    4096          // sequence length
#define EMBD  256
#define HDIRD 256           // HID/2
#define NG    1024          // 4*HDIR
#define TAGS  10
#define NEGV  -10000.0f
#define CL    8             // cluster size per direction
#define HPAD  132           // padded half stride in floats (128+4 -> halves in different banks)
#define HBSTR 264           // one buffer = 2 halves = 264 floats

// ---------------- scratch (device globals; no dynamic alloc) ----------------
__device__ float g_x[SQ * EMBD];              // gathered embeddings   4 MB
__device__ float g_xw[2][SQ * NG];            // input-gate precompute 32 MB
__device__ float g_h[2][SQ * HDIRD];          // hidden states         8 MB
__device__ float g_feats[SQ * TAGS];          // CRF emission feats

// ---------------- helpers ----------------
__device__ __forceinline__ uint32_t smem_u32(const void* p) {
    return (uint32_t)__cvta_generic_to_shared(p);
}
__device__ __forceinline__ uint32_t mapa_u32(uint32_t laddr, uint32_t rank) {
    uint32_t rem;
    asm("mapa.shared::cluster.u32 %0, %1, %2;" : "=r"(rem) : "r"(laddr), "r"(rank));
    return rem;
}
// remote store with completion tx delivered to the DESTINATION CTA's mbarrier
__device__ __forceinline__ void st_async_f32(uint32_t raddr, float v, uint32_t rmbar) {
    asm volatile(
        "st.async.shared::cluster.mbarrier::complete_tx::bytes.b32 [%0], %1, [%2];"
        :: "r"(raddr), "r"(__float_as_uint(v)), "r"(rmbar) : "memory");
}
__device__ __forceinline__ void mbar_init(uint32_t a, uint32_t cnt) {
    asm volatile("mbarrier.init.shared.b64 [%0], %1;" :: "r"(a), "r"(cnt) : "memory");
}
__device__ __forceinline__ void mbar_expect_tx(uint32_t a, uint32_t bytes) {
    asm volatile("mbarrier.arrive.expect_tx.shared.b64 _, [%0], %1;"
                 :: "r"(a), "r"(bytes) : "memory");
}
// exact known-good wait form from ptx_helpers.cuh (local CTA scope)
__device__ __forceinline__ void mbar_wait(uint32_t a, uint32_t par) {
    uint32_t done;
    asm volatile(
        "{\n\t.reg .pred p;\n\t"
        "mbarrier.try_wait.parity.acquire.cta.shared::cta.b64 p, [%1], %2;\n\t"
        "selp.b32 %0, 1, 0, p;\n\t}"
        : "=r"(done) : "r"(a), "r"(par) : "memory");
    if (!done) {
        asm volatile(
            "{\n\t.reg .pred P1;\n\t"
            "WAIT_LOOP_%=:\n\t"
            "mbarrier.try_wait.parity.acquire.cta.shared::cta.b64 P1, [%0], %1, 0x989680;\n\t"
            "@P1 bra.uni WAIT_DONE_%=;\n\t"
            "bra.uni WAIT_LOOP_%=;\n\t"
            "WAIT_DONE_%=:\n\t}"
            :: "r"(a), "r"(par) : "memory");
    }
}
#define CLUSTER_SYNC_() do {                                                   \
    asm volatile("barrier.cluster.arrive.aligned;" ::: "memory");              \
    asm volatile("barrier.cluster.wait.aligned;"   ::: "memory");              \
} while (0)

__device__ __forceinline__ void fma2(unsigned long long& d,
                                     unsigned long long a, unsigned long long b) {
    asm("fma.rn.f32x2 %0, %1, %2, %0;" : "+l"(d) : "l"(a), "l"(b));
}

__device__ __forceinline__ float sigm_f(float x) {
    return 1.0f / (1.0f + __expf(-x));
}
__device__ __forceinline__ float tanh_f(float x) {
    float e = __expf(-2.0f * fabsf(x));
    float r = (1.0f - e) / (1.0f + e);
    return copysignf(r, x);
}

// ---------------- kernel 1: embedding gather ----------------
__global__ void gather_k(const int* __restrict__ sent, const float* __restrict__ emb) {
    int gid = blockIdx.x * blockDim.x + threadIdx.x;  // over SQ*64 float4
    int row = gid >> 6;
    int c   = gid & 63;
    ((float4*)g_x)[row * 64 + c] =
        ((const float4*)emb)[(size_t)sent[row] * 64 + c];
}

// ---------------- kernel 2: xw = x @ Wih^T + (bih+bhh), both directions ----------------
__global__ void xw_gemm_k(const float* __restrict__ Wf, const float* __restrict__ Wb,
                          const float* __restrict__ bihf, const float* __restrict__ bhhf,
                          const float* __restrict__ bihb, const float* __restrict__ bhhb) {
    int d = blockIdx.z;
    const float* W  = d ? Wb : Wf;
    const float* b1 = d ? bihb : bihf;
    const float* b2 = d ? bhhb : bhhf;

    __shared__ float As[32][65];
    __shared__ float Bs[32][65];

    int s0 = blockIdx.x * 64;
    int j0 = blockIdx.y * 64;
    int tid = threadIdx.x;
    int tx = tid & 15, ty = tid >> 4;

    float acc[4][4];
#pragma unroll
    for (int i = 0; i < 4; i++)
#pragma unroll
        for (int j = 0; j < 4; j++) acc[i][j] = 0.0f;

    for (int k0 = 0; k0 < EMBD; k0 += 32) {
#pragma unroll
        for (int i = 0; i < 8; i++) {
            int idx = i * 256 + tid;
            int si = idx >> 5, e = idx & 31;
            As[e][si] = g_x[(s0 + si) * EMBD + k0 + e];
            Bs[e][si] = W[(j0 + si) * EMBD + k0 + e];
        }
        __syncthreads();
#pragma unroll
        for (int e = 0; e < 32; e++) {
            float a[4], bb[4];
#pragma unroll
            for (int i = 0; i < 4; i++) { a[i] = As[e][ty * 4 + i]; bb[i] = Bs[e][tx * 4 + i]; }
#pragma unroll
            for (int i = 0; i < 4; i++)
#pragma unroll
                for (int j = 0; j < 4; j++) acc[i][j] = fmaf(a[i], bb[j], acc[i][j]);
        }
        __syncthreads();
    }
#pragma unroll
    for (int i = 0; i < 4; i++)
#pragma unroll
        for (int j = 0; j < 4; j++) {
            int jj = j0 + tx * 4 + j;
            g_xw[d][(s0 + ty * 4 + i) * NG + jj] = acc[i][j] + b1[jj] + b2[jj];
        }
}

// ---------------- kernel 3: recurrent LSTM, one 8-CTA cluster per direction ----------------
// R8 structure (zbuf + warp0 gates), but per-step cluster.sync replaced by
// st.async completion: warp0 lanes st.async h into all 8 peers' hbuf[b] with
// complete_tx to each destination's mbar[b] (1024 B = 8 CTAs x 32 floats).
// tid0 posts one arrive.expect_tx(1024) per phase; consumers wait LOCALLY
// (try_wait.parity.acquire.cta). Backpressure is implied by dataflow: a peer
// can only overwrite buffer b after passing its wait, which needs my stores,
// which I issue only after my reads of b.
__global__ void __cluster_dims__(CL, 1, 1) __launch_bounds__(256, 1)
lstm_k(const float* __restrict__ Whhf, const float* __restrict__ Whhb) {
    int dir = blockIdx.y;
    const float* Whh = dir ? Whhb : Whhf;
    const float* xw  = g_xw[dir];
    int r   = blockIdx.x;           // cluster rank
    int tid = threadIdx.x;
    int rr   = tid >> 1;            // 0..127 local row
    int half = tid & 1;             // column half
    int gate = rr >> 5;
    int j5   = rr & 31;
    int grow = gate * HDIRD + r * 32 + j5;   // global Whh row / xw column

    // weights -> registers, packed as f32 pairs (half row = 128 cols)
    ulonglong2 Wp[32];
    const ulonglong2* wsrc =
        (const ulonglong2*)(Whh + (size_t)grow * HDIRD + half * 128);
#pragma unroll
    for (int k = 0; k < 32; k++) Wp[k] = wsrc[k];

    __shared__ __align__(16) float hbuf[2 * HBSTR];   // halves padded by 16B
    __shared__ float zbuf[128];
    __shared__ __align__(8) unsigned long long mbs[2]; // mbar per buffer

    for (int i = tid; i < 2 * HBSTR; i += 256) hbuf[i] = 0.0f;
    uint32_t mbb = smem_u32(mbs);
    if (tid == 0) {
        mbar_init(mbb + 0, 1);
        mbar_init(mbb + 8, 1);
    }
    __syncthreads();
    CLUSTER_SYNC_();   // zeroed hbuf + initialized mbarriers visible cluster-wide

    // hoisted remote addresses (used by tid<32): data slot + destination mbar
    uint32_t hb0 = smem_u32(hbuf);
    uint32_t hoff4 = (uint32_t)(r * 32 + (tid & 31) + ((r >= 4) ? 4 : 0)) * 4u;
    uint32_t rh[CL], rmb[CL];
#pragma unroll
    for (int rk = 0; rk < CL; rk++) {
        rh[rk]  = mapa_u32(hb0, rk) + hoff4;
        rmb[rk] = mapa_u32(mbb, rk);
    }

    float c = 0.0f;
    float xwreg = 0.0f;
    int pos0 = dir ? (SQ - 1) : 0;
    if (!half) xwreg = xw[(size_t)pos0 * NG + grow];

    for (int t = 0; t < SQ; t++) {
        int p = t & 1;
        int tn = t + 1;

        // post this phase's expectation for the buffer being filled (p^1)
        if (tid == 0 && tn < SQ)
            mbar_expect_tx(mbb + (uint32_t)((p ^ 1) * 8), 1024u);
        // wait for buffer p to be complete (skip first step: zero-initialized)
        if (t) mbar_wait(mbb + (uint32_t)(p * 8), (uint32_t)(((t - 1) >> 1) & 1));
        __syncthreads();   // all warps see completed buffer; zbuf safe to rewrite

        const ulonglong2* h2 =
            (const ulonglong2*)(hbuf + p * HBSTR + half * HPAD);
        unsigned long long a0 = 0ull, a1 = 0ull;
#pragma unroll
        for (int k = 0; k < 32; k++) {
            ulonglong2 hv = h2[k];
            fma2(a0, Wp[k].x, hv.x);
            fma2(a1, Wp[k].y, hv.y);
        }
        float2 f0 = *(float2*)&a0;
        float2 f1 = *(float2*)&a1;
        float acc = (f0.x + f0.y) + (f1.x + f1.y);
        acc += __shfl_xor_sync(0xffffffffu, acc, 1);   // combine column halves
        if (!half) zbuf[rr] = acc + xwreg;

        // prefetch next step's xw
        if (!half && tn < SQ) {
            int pos = dir ? (SQ - 1 - tn) : tn;
            xwreg = xw[(size_t)pos * NG + grow];
        }
        __syncthreads();   // zbuf ready

        if (tid < 32) {
            float zi = zbuf[tid], zf = zbuf[32 + tid];
            float zg = zbuf[64 + tid], zo = zbuf[96 + tid];
            float ig = sigm_f(zi);
            float fg = sigm_f(zf);
            float gg = tanh_f(zg);
            float og = sigm_f(zo);
            c = fmaf(fg, c, ig * gg);
            float hn = og * tanh_f(c);

            int pos = dir ? (SQ - 1 - t) : t;
            g_h[dir][(size_t)pos * HDIRD + r * 32 + tid] = hn;

            if (tn < SQ) {   // data + completion to every rank (self included)
                uint32_t bo  = (uint32_t)((p ^ 1) * HBSTR * 4);
                uint32_t mbo = (uint32_t)((p ^ 1) * 8);
#pragma unroll
                for (int rk = 0; rk < CL; rk++)
                    st_async_f32(rh[rk] + bo, hn, rmb[rk] + mbo);
            }
        }
        // NO cluster.sync: next iteration's mbar_wait provides ordering.
    }
    CLUSTER_SYNC_();   // keep SMEM alive until all peers are done
}

// ---------------- kernel 4: feats = [h_f | h_b] @ Wout^T + b (warp per s) ----------------
__global__ void feats_k(const float* __restrict__ Wout, const float* __restrict__ bout) {
    __shared__ float Wsm[TAGS][512];
    __shared__ float bsm[TAGS];
    int tid = threadIdx.x;
    for (int i = tid; i < TAGS * 512; i += 256) Wsm[i / 512][i % 512] = Wout[i];
    if (tid < TAGS) bsm[tid] = bout[tid];
    __syncthreads();

    int lane = tid & 31;
    int s = blockIdx.x * 8 + (tid >> 5);     // warp per sequence position
    float acc[TAGS];
#pragma unroll
    for (int t = 0; t < TAGS; t++) acc[t] = 0.0f;

#pragma unroll
    for (int d = 0; d < 2; d++) {
        const float* hrow = (d == 0) ? &g_h[0][(size_t)s * HDIRD]
                                     : &g_h[1][(size_t)s * HDIRD];
#pragma unroll
        for (int k0 = 0; k0 < HDIRD; k0 += 32) {
            float x = hrow[k0 + lane];
#pragma unroll
            for (int t = 0; t < TAGS; t++)
                acc[t] = fmaf(x, Wsm[t][d * 256 + k0 + lane], acc[t]);
        }
    }
#pragma unroll
    for (int t = 0; t < TAGS; t++) {
#pragma unroll
        for (int o = 16; o > 0; o >>= 1) acc[t] += __shfl_xor_sync(0xffffffffu, acc[t], o);
    }
    if (lane == 0) {
#pragma unroll
        for (int t = 0; t < TAGS; t++) g_feats[s * TAGS + t] = acc[t] + bsm[t];
    }
}

// ---------------- kernel 5: Viterbi decode (single warp) ----------------
__global__ void viterbi_k(const float* __restrict__ trans, float* __restrict__ out,
                          int out_size) {
    __shared__ unsigned char bp[SQ][TAGS];   // 40 KB backpointers
    int n = threadIdx.x;

    float tr[TAGS];
#pragma unroll
    for (int p = 0; p < TAGS; p++) tr[p] = (n < TAGS) ? trans[n * TAGS + p] : NEGV;

    float fvr = (n == 8) ? 0.0f : NEGV;      // START = 8
    float fa = (n < TAGS) ? g_feats[0 * TAGS + n] : 0.0f;
    float fb = (n < TAGS) ? g_feats[1 * TAGS + n] : 0.0f;

    for (int t = 0; t < SQ; t++) {
        float m = -3.4e38f;
        int bi = 0;
#pragma unroll
        for (int p = 0; p < TAGS; p++) {
            float v = __shfl_sync(0xffffffffu, fvr, p) + tr[p];
            if (v > m) { m = v; bi = p; }    // strict > keeps first max (jnp.argmax)
        }
        if (n < TAGS) bp[t][n] = (unsigned char)bi;
        float nf = m + fa;
        fa = fb;
        int tn = t + 2;
        if (n < TAGS && tn < SQ) fb = g_feats[tn * TAGS + n];
        fvr = nf;
    }

    float term = fvr + ((n < TAGS) ? trans[9 * TAGS + n] : NEGV);
    float bm = -3.4e38f;
    int bidx = 0;
#pragma unroll
    for (int p = 0; p < TAGS; p++) {
        float v = __shfl_sync(0xffffffffu, term, p);
        if (v > bm) { bm = v; bidx = p; }
    }
    if (n == 0) {
        int off = (out_size > SQ) ? 1 : 0;
        if (off) out[0] = bm;                // score first, then path
        int tag = bidx;
        for (int t = SQ - 1; t >= 0; t--) {
            out[off + t] = (float)tag;
            tag = bp[t][tag];
        }
    }
}

// ---------------- launch ----------------
extern "C" void kernel_launch(void* const* d_in, const int* in_sizes, int n_in,
                              void* d_out, int out_size) {
    const int*   sent  = (const int*)d_in[0];
    const float* emb   = (const float*)d_in[1];
    const float* Wih_f = (const float*)d_in[2];
    const float* Whh_f = (const float*)d_in[3];
    const float* bih_f = (const float*)d_in[4];
    const float* bhh_f = (const float*)d_in[5];
    const float* Wih_b = (const float*)d_in[6];
    const float* Whh_b = (const float*)d_in[7];
    const float* bih_b = (const float*)d_in[8];
    const float* bhh_b = (const float*)d_in[9];
    const float* W_out = (const float*)d_in[10];
    const float* b_out = (const float*)d_in[11];
    const float* trans = (const float*)d_in[12];
    float* out = (float*)d_out;

    gather_k<<<(SQ * 64) / 256, 256>>>(sent, emb);
    xw_gemm_k<<<dim3(SQ / 64, NG / 64, 2), 256>>>(Wih_f, Wih_b, bih_f, bhh_f, bih_b, bhh_b);
    lstm_k<<<dim3(CL, 2, 1), 256>>>(Whh_f, Whh_b);
    feats_k<<<SQ / 8, 256>>>(W_out, b_out);   // 512 blocks x 8 warps = 4096 positions
    viterbi_k<<<1, 32>>>(trans, out, out_size);
}